// round 8
// baseline (speedup 1.0000x reference)
#include <cuda_runtime.h>
#include <cuda_fp16.h>
#include <cstdint>

// Problem constants
#define N_ROWS 16384
#define KNB    25
#define DIM    512
#define ODIM   1024

// GEMM tile (small -> 64 regs -> 4 CTAs/SM)
#define BM 64
#define BN 64
#define BK 32
#define SROW 40                      // halves per smem row (80B) -> conflict-free ldmatrix
#define NKT (DIM / BK)               // 16
#define STAGE_A (BM * SROW)          // 2560 halves
#define STAGE_B (BN * SROW)          // 2560 halves
#define STAGE_HALVES (STAGE_A + STAGE_B)
#define SMEM_BYTES (2 * STAGE_HALVES * 2)   // 20480 B (2 stages)

// Work decomposition
#define W_UNITS 32                   // 4 x (64x64) transpose tiles each
#define MEAN_UNITS 2048              // 8 rows each
#define UNITS_TOTAL (W_UNITS + MEAN_UNITS)
#define UNITS_PER_MB 8               // 64 rows / 8
#define NUM_MB 256                   // 16384 / 64
#define GEMM_ITEMS 4096              // mb = g>>4, nb = g&15
#define GRID_CTAS 592                // 4 CTAs/SM x 148 SMs

// Scratch + control (device globals — no allocation allowed)
__device__ __half g_A [N_ROWS * DIM];
__device__ __half g_WT[ODIM  * DIM];
__device__ int g_unit_next, g_gemm_next, g_wcount;
__device__ int g_mb_count[NUM_MB];

// ---------------------------------------------------------------------------
__global__ void __launch_bounds__(256) zero_kernel()
{
    int t = threadIdx.x;
    if (t < NUM_MB) g_mb_count[t] = 0;
    if (t == 0) g_unit_next = 0;
    if (t == 1) g_gemm_next = 0;
    if (t == 2) g_wcount = 0;
}

// ---------------------------------------------------------------------------
// helpers
// ---------------------------------------------------------------------------
__device__ __forceinline__ uint32_t smem_addr32(const void* p) {
    return (uint32_t)__cvta_generic_to_shared(p);
}
__device__ __forceinline__ void ldmatrix_x4(uint32_t& r0, uint32_t& r1,
                                            uint32_t& r2, uint32_t& r3, uint32_t addr) {
    asm volatile("ldmatrix.sync.aligned.m8n8.x4.shared.b16 {%0,%1,%2,%3}, [%4];"
                 : "=r"(r0), "=r"(r1), "=r"(r2), "=r"(r3) : "r"(addr));
}
__device__ __forceinline__ void mma16816(float* c, const uint32_t* a, const uint32_t* b) {
    asm volatile(
        "mma.sync.aligned.m16n8k16.row.col.f32.f16.f16.f32 "
        "{%0,%1,%2,%3}, {%4,%5,%6,%7}, {%8,%9}, {%0,%1,%2,%3};"
        : "+f"(c[0]), "+f"(c[1]), "+f"(c[2]), "+f"(c[3])
        : "r"(a[0]), "r"(a[1]), "r"(a[2]), "r"(a[3]), "r"(b[0]), "r"(b[1]));
}
__device__ __forceinline__ void cp_async16(uint32_t dst, const void* src) {
    asm volatile("cp.async.cg.shared.global [%0], [%1], 16;" :: "r"(dst), "l"(src));
}

// ---------------------------------------------------------------------------
// W transpose unit: 4 tiles of 64x64, staged in dyn smem (pad 65)
// ---------------------------------------------------------------------------
__device__ void do_w_unit(int u, const float* __restrict__ W, __half* stage, int tid)
{
    #pragma unroll 1
    for (int j = 0; j < 4; j++) {
        int i = u * 4 + j;
        int bk = i & 7, bo = i >> 3;
        #pragma unroll 4
        for (int p = 0; p < 16; p++) {
            int idx = tid + p * 256;
            int kk = idx >> 6, oo = idx & 63;
            stage[kk * 65 + oo] =
                __float2half_rn(W[(size_t)(bk * 64 + kk) * ODIM + bo * 64 + oo]);
        }
        __syncthreads();
        #pragma unroll 4
        for (int p = 0; p < 16; p++) {
            int idx = tid + p * 256;
            int oo = idx >> 6, kk = idx & 63;
            g_WT[(size_t)(bo * 64 + oo) * DIM + bk * 64 + kk] = stage[kk * 65 + oo];
        }
        __syncthreads();
    }
}

// ---------------------------------------------------------------------------
// Mean unit: 8 rows; 256 threads = 2 rows per pass, 4 passes
// ---------------------------------------------------------------------------
__device__ void do_mean_unit(int m, const float* __restrict__ self_vecs,
                             const float* __restrict__ neigh, int tid)
{
    int lane = tid & 127;
    #pragma unroll
    for (int p = 0; p < 4; p++) {
        int r = m * 8 + p * 2 + (tid >> 7);
        const float4* sv = (const float4*)self_vecs + (size_t)r * 128;
        const float4* nv = (const float4*)neigh + ((size_t)r * KNB) * 128;
        float4 acc = sv[lane];
        #pragma unroll 5
        for (int k = 0; k < KNB; k++) {
            float4 v = nv[(size_t)k * 128 + lane];
            acc.x += v.x; acc.y += v.y; acc.z += v.z; acc.w += v.w;
        }
        const float inv = 1.0f / (float)(KNB + 1);
        acc.x *= inv; acc.y *= inv; acc.z *= inv; acc.w *= inv;
        __half2* o = (__half2*)g_A + (size_t)r * 256;
        o[lane * 2 + 0] = __floats2half2_rn(acc.x, acc.y);
        o[lane * 2 + 1] = __floats2half2_rn(acc.z, acc.w);
    }
}

// ---------------------------------------------------------------------------
// GEMM item: 64x64 output tile, 2-stage cp.async, fp16 mma, bias+relu
// 8 warps: warp_m = wid&3 (16 rows), warp_n = wid>>2 (32 cols)
// ---------------------------------------------------------------------------
__device__ void do_gemm(int mb, int nb, const float* __restrict__ bias,
                        float* __restrict__ out, __half* dyn, int tid)
{
    int wid = tid >> 5;
    int lane = tid & 31;
    int warp_m = wid & 3;
    int warp_n = wid >> 2;
    int m0 = mb * BM;
    int n0 = nb * BN;

    const __half* gA = g_A  + (size_t)m0 * DIM;
    const __half* gB = g_WT + (size_t)n0 * DIM;

    uint32_t base = smem_addr32(dyn);
    uint32_t sAb[2] = { base, base + STAGE_HALVES * 2 };
    uint32_t sBb[2] = { base + STAGE_A * 2, base + STAGE_HALVES * 2 + STAGE_A * 2 };

    // cp.async: 1 chunk/thread for A, 1 for B (64 rows x 32 cols each)
    int c_r = tid >> 2, c_c = (tid & 3) * 8;

    float acc[4][4];
    #pragma unroll
    for (int j = 0; j < 4; j++)
        #pragma unroll
        for (int v = 0; v < 4; v++) acc[j][v] = 0.0f;

    int a_row = warp_m * 16 + (lane & 15);
    int a_colb = ((lane >> 4) << 3);
    int quad = lane >> 3;
    int b_row_off = ((quad >> 1) << 3) + (lane & 7);
    int b_colb = ((quad & 1) << 3);

    cp_async16(sAb[0] + (c_r * SROW + c_c) * 2, gA + (size_t)c_r * DIM + c_c);
    cp_async16(sBb[0] + (c_r * SROW + c_c) * 2, gB + (size_t)c_r * DIM + c_c);
    asm volatile("cp.async.commit_group;");

    #pragma unroll 2
    for (int kt = 0; kt < NKT; kt++) {
        if (kt + 1 < NKT) {
            int s = (kt + 1) & 1;
            int kb = (kt + 1) * BK;
            cp_async16(sAb[s] + (c_r * SROW + c_c) * 2, gA + (size_t)c_r * DIM + kb + c_c);
            cp_async16(sBb[s] + (c_r * SROW + c_c) * 2, gB + (size_t)c_r * DIM + kb + c_c);
            asm volatile("cp.async.commit_group;");
            asm volatile("cp.async.wait_group 1;");
        } else {
            asm volatile("cp.async.wait_group 0;");
        }
        __syncthreads();

        int s = kt & 1;
        #pragma unroll
        for (int ks = 0; ks < 2; ks++) {
            uint32_t af[4];
            {
                uint32_t addr = sAb[s] + (a_row * SROW + ks * 16 + a_colb) * 2;
                ldmatrix_x4(af[0], af[1], af[2], af[3], addr);
            }
            uint32_t bf[4][2];
            #pragma unroll
            for (int ntp = 0; ntp < 2; ntp++) {
                uint32_t r0, r1, r2, r3;
                uint32_t addr = sBb[s] +
                    ((warp_n * 32 + ntp * 16 + b_row_off) * SROW + ks * 16 + b_colb) * 2;
                ldmatrix_x4(r0, r1, r2, r3, addr);
                bf[ntp * 2 + 0][0] = r0; bf[ntp * 2 + 0][1] = r1;
                bf[ntp * 2 + 1][0] = r2; bf[ntp * 2 + 1][1] = r3;
            }
            #pragma unroll
            for (int nt = 0; nt < 4; nt++)
                mma16816(acc[nt], af, bf[nt]);
        }
        __syncthreads();
    }

    #pragma unroll
    for (int nt = 0; nt < 4; nt++) {
        int col = n0 + warp_n * 32 + nt * 8 + ((lane & 3) << 1);
        float b0 = bias[col], b1 = bias[col + 1];
        int row = m0 + warp_m * 16 + (lane >> 2);
        float2 v0, v1;
        v0.x = fmaxf(acc[nt][0] + b0, 0.0f);
        v0.y = fmaxf(acc[nt][1] + b1, 0.0f);
        v1.x = fmaxf(acc[nt][2] + b0, 0.0f);
        v1.y = fmaxf(acc[nt][3] + b1, 0.0f);
        *(float2*)(out + (size_t)row * ODIM + col) = v0;
        *(float2*)(out + (size_t)(row + 8) * ODIM + col) = v1;
    }
}

// ---------------------------------------------------------------------------
// Fused persistent kernel: claim GEMM item; help with mean/W units until ready
// ---------------------------------------------------------------------------
__global__ void __launch_bounds__(256, 4) fused_kernel(
    const float* __restrict__ self_vecs, const float* __restrict__ neigh,
    const float* __restrict__ W, const float* __restrict__ bias,
    float* __restrict__ out)
{
    extern __shared__ __half dyn[];
    __shared__ int s_b;
    int tid = threadIdx.x;

    for (;;) {
        __syncthreads();
        if (tid == 0) s_b = atomicAdd(&g_gemm_next, 1);
        __syncthreads();
        int g = s_b;
        if (g >= GEMM_ITEMS) return;          // uniform per CTA
        int mb = g >> 4;
        int nb = g & 15;

        // help with producer work until this item's inputs are ready
        for (;;) {
            __syncthreads();
            if (tid == 0) {
                bool ready = (atomicAdd(&g_wcount, 0) == W_UNITS) &&
                             (atomicAdd(&g_mb_count[mb], 0) == UNITS_PER_MB);
                s_b = ready ? -1 : atomicAdd(&g_unit_next, 1);
            }
            __syncthreads();
            int u = s_b;
            if (u < 0) break;
            if (u < W_UNITS) {
                do_w_unit(u, W, dyn, tid);
                __syncthreads();
                if (tid == 0) { __threadfence(); atomicAdd(&g_wcount, 1); }
            } else if (u < UNITS_TOTAL) {
                int m = u - W_UNITS;
                do_mean_unit(m, self_vecs, neigh, tid);
                __syncthreads();
                if (tid == 0) {
                    __threadfence();
                    atomicAdd(&g_mb_count[m >> 3], 1);
                }
            } else {
                if (tid == 0) __nanosleep(256);   // all producer work claimed; poll
            }
        }
        __threadfence();                       // order flag read before g_A/g_WT reads
        do_gemm(mb, nb, bias, out, dyn, tid);
    }
}

// ---------------------------------------------------------------------------
// Launch
// ---------------------------------------------------------------------------
extern "C" void kernel_launch(void* const* d_in, const int* in_sizes, int n_in,
                              void* d_out, int out_size)
{
    const float* self_vecs = (const float*)d_in[0];   // [16384, 512]
    const float* neigh     = (const float*)d_in[1];   // [16384, 25, 512]
    // d_in[2] = temperature (unused by reference)
    const float* W         = (const float*)d_in[3];   // [512, 1024]
    const float* b         = (const float*)d_in[4];   // [1024]
    float* out = (float*)d_out;                       // [16384, 1024]

    zero_kernel<<<1, 256>>>();
    fused_kernel<<<GRID_CTAS, 256, SMEM_BYTES>>>(self_vecs, neigh, W, b, out);
}

// round 9
// speedup vs baseline: 1.1681x; 1.1681x over previous
#include <cuda_runtime.h>
#include <cuda_fp16.h>
#include <cstdint>

// Problem constants
#define N_ROWS 16384
#define KNB    25
#define DIM    512
#define ODIM   1024

// GEMM tiling (R5 baseline, unchanged)
#define BM 128
#define BN 128
#define BK 32
#define SROW 40            // smem row stride in halves (80B): ldmatrix conflict-free
#define STAGES 3
#define NKT (DIM / BK)     // 16

#define TILE_HALVES (BM * SROW)                    // 5120 halves per tile
#define SMEM_BYTES  (STAGES * 2 * TILE_HALVES * 2) // 61440 bytes

// Scratch (device globals — no allocation allowed)
__device__ __half g_A [N_ROWS * DIM];   // fp16 means, [N, D] row-major
__device__ __half g_WT[ODIM  * DIM];    // fp16 W^T,   [O, D] K-major

// ---------------------------------------------------------------------------
// Kernel 1: W[D=512, O=1024] fp32 -> g_WT[O, D] fp16, tiled smem transpose.
// ---------------------------------------------------------------------------
__global__ void __launch_bounds__(256) wprep_kernel(const float* __restrict__ W)
{
    __shared__ __half s[64 * 65];
    int bk = blockIdx.x & 7;     // 8 k-tiles (512/64)
    int bo = blockIdx.x >> 3;    // 16 o-tiles (1024/64)
    int tid = threadIdx.x;

    #pragma unroll
    for (int i = 0; i < 16; i++) {
        int idx = tid + i * 256;
        int kk = idx >> 6, oo = idx & 63;
        s[kk * 65 + oo] = __float2half_rn(W[(size_t)(bk * 64 + kk) * ODIM + bo * 64 + oo]);
    }
    __syncthreads();
    #pragma unroll
    for (int i = 0; i < 16; i++) {
        int idx = tid + i * 256;
        int oo = idx >> 6, kk = idx & 63;
        g_WT[(size_t)(bo * 64 + oo) * DIM + bk * 64 + kk] = s[kk * 65 + oo];
    }
}

// ---------------------------------------------------------------------------
// Kernel 2 (v3): means -> fp16.  256 threads = 2 rows/block.
// Front-batched load window (MLP ~25) + __ldcs evict-first streaming.
// ---------------------------------------------------------------------------
__global__ void __launch_bounds__(256, 2) mean_kernel(const float* __restrict__ self_vecs,
                                                      const float* __restrict__ neigh)
{
    int r = blockIdx.x * 2 + (threadIdx.x >> 7);
    int t = threadIdx.x & 127;

    const float4* nv = (const float4*)neigh + (size_t)r * KNB * (DIM / 4) + t;
    float4 acc = __ldg((const float4*)self_vecs + (size_t)r * (DIM / 4) + t);

    // stage all 25 loads first (front-batched -> deep MLP), then reduce
    float4 v[KNB];
    #pragma unroll
    for (int k = 0; k < KNB; k++)
        v[k] = __ldcs(nv + (size_t)k * (DIM / 4));

    #pragma unroll
    for (int k = 0; k < KNB; k++) {
        acc.x += v[k].x; acc.y += v[k].y; acc.z += v[k].z; acc.w += v[k].w;
    }
    const float inv = 1.0f / (float)(KNB + 1);
    acc.x *= inv; acc.y *= inv; acc.z *= inv; acc.w *= inv;

    __half2* out = (__half2*)g_A + (size_t)r * (DIM / 2);
    out[t * 2 + 0] = __floats2half2_rn(acc.x, acc.y);
    out[t * 2 + 1] = __floats2half2_rn(acc.z, acc.w);
}

// ---------------------------------------------------------------------------
// mma.sync helpers
// ---------------------------------------------------------------------------
__device__ __forceinline__ uint32_t smem_addr32(const void* p) {
    return (uint32_t)__cvta_generic_to_shared(p);
}

__device__ __forceinline__ void ldmatrix_x4(uint32_t& r0, uint32_t& r1,
                                            uint32_t& r2, uint32_t& r3, uint32_t addr) {
    asm volatile("ldmatrix.sync.aligned.m8n8.x4.shared.b16 {%0,%1,%2,%3}, [%4];"
                 : "=r"(r0), "=r"(r1), "=r"(r2), "=r"(r3) : "r"(addr));
}

__device__ __forceinline__ void mma16816(float* c, const uint32_t* a, const uint32_t* b) {
    asm volatile(
        "mma.sync.aligned.m16n8k16.row.col.f32.f16.f16.f32 "
        "{%0,%1,%2,%3}, {%4,%5,%6,%7}, {%8,%9}, {%0,%1,%2,%3};"
        : "+f"(c[0]), "+f"(c[1]), "+f"(c[2]), "+f"(c[3])
        : "r"(a[0]), "r"(a[1]), "r"(a[2]), "r"(a[3]), "r"(b[0]), "r"(b[1]));
}

__device__ __forceinline__ void cp_async16(uint32_t dst, const void* src) {
    asm volatile("cp.async.cg.shared.global [%0], [%1], 16;" :: "r"(dst), "l"(src));
}

// ---------------------------------------------------------------------------
// Kernel 3: out = relu(A_fp16 @ WT_fp16^T + b)  — R5 baseline, unchanged
// ---------------------------------------------------------------------------
__global__ void __launch_bounds__(256, 2) gemm_kernel(const float* __restrict__ bias,
                                                      float* __restrict__ out)
{
    extern __shared__ __half smem_dyn[];
    int tid = threadIdx.x;
    int wid = tid >> 5;
    int lane = tid & 31;
    int warp_m = wid & 3;
    int warp_n = wid >> 2;
    int m0 = blockIdx.x * BM;
    int n0 = blockIdx.y * BN;

    const __half* gA = g_A  + (size_t)m0 * DIM;
    const __half* gB = g_WT + (size_t)n0 * DIM;

    float acc[2][8][4];
    #pragma unroll
    for (int i = 0; i < 2; i++)
        #pragma unroll
        for (int j = 0; j < 8; j++)
            #pragma unroll
            for (int v = 0; v < 4; v++) acc[i][j][v] = 0.0f;

    uint32_t sA_base[STAGES], sB_base[STAGES];
    uint32_t sdyn = smem_addr32(smem_dyn);
    #pragma unroll
    for (int s = 0; s < STAGES; s++) {
        sA_base[s] = sdyn + (uint32_t)(s * TILE_HALVES) * 2u;
        sB_base[s] = sdyn + (uint32_t)((STAGES + s) * TILE_HALVES) * 2u;
    }

    int cp_row = tid >> 2;
    int cp_c   = (tid & 3) * 8;
    int cp_row2 = (tid + 256) >> 2;
    int cp_c2   = ((tid + 256) & 3) * 8;

    int a_row = warp_m * 32 + (lane & 15);
    int a_colb = ((lane >> 4) << 3);
    int quad = lane >> 3;
    int b_row_off = ((quad >> 1) << 3) + (lane & 7);
    int b_colb = ((quad & 1) << 3);

    #pragma unroll
    for (int p = 0; p < 2; p++) {
        int kb = p * BK;
        cp_async16(sA_base[p] + (cp_row  * SROW + cp_c ) * 2, gA + (size_t)cp_row  * DIM + kb + cp_c );
        cp_async16(sA_base[p] + (cp_row2 * SROW + cp_c2) * 2, gA + (size_t)cp_row2 * DIM + kb + cp_c2);
        cp_async16(sB_base[p] + (cp_row  * SROW + cp_c ) * 2, gB + (size_t)cp_row  * DIM + kb + cp_c );
        cp_async16(sB_base[p] + (cp_row2 * SROW + cp_c2) * 2, gB + (size_t)cp_row2 * DIM + kb + cp_c2);
        asm volatile("cp.async.commit_group;");
    }

    #pragma unroll 4
    for (int kt = 0; kt < NKT; kt++) {
        asm volatile("cp.async.wait_group 1;");
        __syncthreads();

        if (kt + 2 < NKT) {
            int buf = (kt + 2) % STAGES;
            int kb = (kt + 2) * BK;
            cp_async16(sA_base[buf] + (cp_row  * SROW + cp_c ) * 2, gA + (size_t)cp_row  * DIM + kb + cp_c );
            cp_async16(sA_base[buf] + (cp_row2 * SROW + cp_c2) * 2, gA + (size_t)cp_row2 * DIM + kb + cp_c2);
            cp_async16(sB_base[buf] + (cp_row  * SROW + cp_c ) * 2, gB + (size_t)cp_row  * DIM + kb + cp_c );
            cp_async16(sB_base[buf] + (cp_row2 * SROW + cp_c2) * 2, gB + (size_t)cp_row2 * DIM + kb + cp_c2);
        }
        asm volatile("cp.async.commit_group;");

        int buf = kt % STAGES;
        #pragma unroll
        for (int ks = 0; ks < 2; ks++) {
            uint32_t af[2][4];
            #pragma unroll
            for (int mt = 0; mt < 2; mt++) {
                uint32_t addr = sA_base[buf] +
                    ((a_row + mt * 16) * SROW + ks * 16 + a_colb) * 2;
                ldmatrix_x4(af[mt][0], af[mt][1], af[mt][2], af[mt][3], addr);
            }
            uint32_t bf[8][2];
            #pragma unroll
            for (int ntp = 0; ntp < 4; ntp++) {
                uint32_t r0, r1, r2, r3;
                uint32_t addr = sB_base[buf] +
                    ((warp_n * 64 + ntp * 16 + b_row_off) * SROW + ks * 16 + b_colb) * 2;
                ldmatrix_x4(r0, r1, r2, r3, addr);
                bf[ntp * 2 + 0][0] = r0; bf[ntp * 2 + 0][1] = r1;
                bf[ntp * 2 + 1][0] = r2; bf[ntp * 2 + 1][1] = r3;
            }
            #pragma unroll
            for (int mt = 0; mt < 2; mt++)
                #pragma unroll
                for (int nt = 0; nt < 8; nt++)
                    mma16816(acc[mt][nt], af[mt], bf[nt]);
        }
    }

    #pragma unroll
    for (int nt = 0; nt < 8; nt++) {
        int col = n0 + warp_n * 64 + nt * 8 + ((lane & 3) << 1);
        float b0 = bias[col], b1 = bias[col + 1];
        #pragma unroll
        for (int mt = 0; mt < 2; mt++) {
            int row = m0 + warp_m * 32 + mt * 16 + (lane >> 2);
            float2 v0, v1;
            v0.x = fmaxf(acc[mt][nt][0] + b0, 0.0f);
            v0.y = fmaxf(acc[mt][nt][1] + b1, 0.0f);
            v1.x = fmaxf(acc[mt][nt][2] + b0, 0.0f);
            v1.y = fmaxf(acc[mt][nt][3] + b1, 0.0f);
            *(float2*)(out + (size_t)row * ODIM + col) = v0;
            *(float2*)(out + (size_t)(row + 8) * ODIM + col) = v1;
        }
    }
}

// ---------------------------------------------------------------------------
// Launch
// ---------------------------------------------------------------------------
extern "C" void kernel_launch(void* const* d_in, const int* in_sizes, int n_in,
                              void* d_out, int out_size)
{
    const float* self_vecs = (const float*)d_in[0];   // [16384, 512]
    const float* neigh     = (const float*)d_in[1];   // [16384, 25, 512]
    // d_in[2] = temperature (unused by reference)
    const float* W         = (const float*)d_in[3];   // [512, 1024]
    const float* b         = (const float*)d_in[4];   // [1024]
    float* out = (float*)d_out;                       // [16384, 1024]

    static bool attr_set = false;
    if (!attr_set) {
        cudaFuncSetAttribute(gemm_kernel, cudaFuncAttributeMaxDynamicSharedMemorySize,
                             SMEM_BYTES);
        attr_set = true;
    }

    wprep_kernel<<<128, 256>>>(W);
    mean_kernel<<<N_ROWS / 2, 256>>>(self_vecs, neigh);
    dim3 gg(N_ROWS / BM, ODIM / BN);
    gemm_kernel<<<gg, 256, SMEM_BYTES>>>(b, out);
}